// round 2
// baseline (speedup 1.0000x reference)
#include <cuda_runtime.h>

#define BATCH 64
#define H0 256
#define W0 256
#define H1 128
#define W1 128
#define NPIX0 (H0*W0)
#define NPIX1 (H1*W1)

// ---------------- scratch (device globals: no allocations allowed) ----------
__device__ float g_t2[BATCH*16*NPIX1];    // conv2 out (67 MB)
__device__ float g_t3[BATCH*16*NPIX1];    // conv3 out (67 MB)
__device__ float g_part[BATCH*16*64];     // per-16x16-tile sums of fb
__device__ float g_phi[BATCH*3];          // combined head coefficients
__device__ float g_tmp[BATCH*NPIX0];      // horizontal blur intermediate (17 MB)

// =====================================================================
// Fused conv1 (3->16, 3x3, s1, SAME, relu) + conv2 (16->16, 3x3, s2,
// SAME pad_lo=0, relu). One block computes a 16x16 output tile of conv2
// at 128^2. conv1 is computed into smem over the 33x33 halo, in two
// chunks of 8 channels to bound smem.
// smem: s_x 3*35*36, s_mid 8*33*34, s_w1 27*16, s_w2 144*16, biases.
// =====================================================================
#define C12_SMEM_FLOATS (3*35*36 + 8*33*34 + 27*16 + 144*16 + 32)

__global__ void conv12_kernel(const float* __restrict__ x,
                              const float* __restrict__ w1,
                              const float* __restrict__ b1,
                              const float* __restrict__ w2,
                              const float* __restrict__ b2) {
    extern __shared__ float sm[];
    float* s_x   = sm;                     // [3][35][36]
    float* s_mid = s_x + 3*35*36;          // [8][33][34]
    float* s_w1  = s_mid + 8*33*34;        // [27][16]
    float* s_w2  = s_w1 + 27*16;           // [144][16]
    float* s_b1  = s_w2 + 144*16;          // [16]
    float* s_b2  = s_b1 + 16;              // [16]

    const int b = blockIdx.z;
    const int oy0 = blockIdx.y * 16, ox0 = blockIdx.x * 16;
    const int iy0 = oy0 * 2, ix0 = ox0 * 2;      // conv1-space tile origin
    const int tid = threadIdx.y * 16 + threadIdx.x;
    const int ty = threadIdx.y, tx = threadIdx.x;

    // weights
    for (int i = tid; i < 27*16; i += 256) {
        int oc = i & 15, k = i >> 4;
        s_w1[k*16 + oc] = w1[oc*27 + k];
    }
    for (int i = tid; i < 144*16; i += 256) {
        int oc = i & 15, k = i >> 4;
        s_w2[k*16 + oc] = w2[oc*144 + k];
    }
    if (tid < 16) { s_b1[tid] = b1[tid]; s_b2[tid] = b2[tid]; }

    // x halo: rows iy0-1 .. iy0+33, cols ix0-1 .. ix0+33 (35x35), zero pad
    for (int i = tid; i < 3*35*35; i += 256) {
        int c = i / 1225, r = i % 1225;
        int yy = r / 35, xx = r % 35;
        int gy = iy0 + yy - 1, gx = ix0 + xx - 1;
        float v = 0.f;
        if (gy >= 0 && gy < H0 && gx >= 0 && gx < W0)
            v = x[((b*3 + c)*H0 + gy)*W0 + gx];
        s_x[(c*35 + yy)*36 + xx] = v;
    }

    float acc2[16];
    #pragma unroll
    for (int oc = 0; oc < 16; oc++) acc2[oc] = 0.f;

    for (int occ = 0; occ < 16; occ += 8) {
        __syncthreads();
        // ---- conv1 for channels occ..occ+7 over 33x33 positions ----
        for (int i = tid; i < 33*33; i += 256) {
            int yy = i / 33, xx = i % 33;
            float a[8];
            #pragma unroll
            for (int j = 0; j < 8; j++) a[j] = s_b1[occ + j];
            #pragma unroll
            for (int c = 0; c < 3; c++)
                #pragma unroll
                for (int ky = 0; ky < 3; ky++)
                    #pragma unroll
                    for (int kx = 0; kx < 3; kx++) {
                        float v = s_x[(c*35 + yy + ky)*36 + xx + kx];
                        const float* wr = &s_w1[(c*9 + ky*3 + kx)*16 + occ];
                        #pragma unroll
                        for (int j = 0; j < 8; j++) a[j] = fmaf(v, wr[j], a[j]);
                    }
            // mask positions beyond image edge (conv2 SAME pad_hi = 1)
            bool valid = (iy0 + yy < H0) && (ix0 + xx < W0);
            #pragma unroll
            for (int j = 0; j < 8; j++)
                s_mid[(j*33 + yy)*34 + xx] = valid ? fmaxf(a[j], 0.f) : 0.f;
        }
        __syncthreads();
        // ---- conv2 partial accumulation over these 8 input channels ----
        #pragma unroll
        for (int c = 0; c < 8; c++)
            #pragma unroll
            for (int ky = 0; ky < 3; ky++)
                #pragma unroll
                for (int kx = 0; kx < 3; kx++) {
                    float v = s_mid[(c*33 + 2*ty + ky)*34 + 2*tx + kx];
                    const float* wr = &s_w2[((occ + c)*9 + ky*3 + kx)*16];
                    #pragma unroll
                    for (int oc = 0; oc < 16; oc++) acc2[oc] = fmaf(v, wr[oc], acc2[oc]);
                }
    }

    const int oy = oy0 + ty, ox = ox0 + tx;
    #pragma unroll
    for (int oc = 0; oc < 16; oc++)
        g_t2[((b*16 + oc)*H1 + oy)*W1 + ox] = fmaxf(acc2[oc] + s_b2[oc], 0.f);
}

// ---------------- conv3: 16->16, 3x3, stride 1, SAME, relu ------------------
__global__ void conv3_kernel(const float* __restrict__ w,
                             const float* __restrict__ bias) {
    __shared__ float s_in[16][18][18];
    __shared__ float s_w[144][16];
    __shared__ float s_b[16];
    const int b = blockIdx.z;
    const int ox0 = blockIdx.x * 16, oy0 = blockIdx.y * 16;
    const int tid = threadIdx.y * 16 + threadIdx.x;

    for (int i = tid; i < 16 * 144; i += 256) {
        int oc = i & 15, k = i >> 4;
        s_w[k][oc] = w[oc * 144 + k];
    }
    if (tid < 16) s_b[tid] = bias[tid];
    for (int i = tid; i < 16 * 324; i += 256) {
        int c = i / 324, r = i % 324;
        int yy = r / 18, xx = r % 18;
        int gy = oy0 + yy - 1, gx = ox0 + xx - 1;
        float v = 0.f;
        if (gy >= 0 && gy < H1 && gx >= 0 && gx < W1)
            v = g_t2[((b * 16 + c) * H1 + gy) * W1 + gx];
        s_in[c][yy][xx] = v;
    }
    __syncthreads();

    const int ty = threadIdx.y, tx = threadIdx.x;
    float acc[16];
    #pragma unroll
    for (int oc = 0; oc < 16; oc++) acc[oc] = s_b[oc];
    #pragma unroll
    for (int c = 0; c < 16; c++)
        #pragma unroll
        for (int ky = 0; ky < 3; ky++)
            #pragma unroll
            for (int kx = 0; kx < 3; kx++) {
                float v = s_in[c][ty + ky][tx + kx];
                const float* wr = &s_w[c * 9 + ky * 3 + kx][0];
                #pragma unroll
                for (int oc = 0; oc < 16; oc++) acc[oc] = fmaf(v, wr[oc], acc[oc]);
            }
    const int oy = oy0 + ty, ox = ox0 + tx;
    #pragma unroll
    for (int oc = 0; oc < 16; oc++)
        g_t3[((b * 16 + oc) * H1 + oy) * W1 + ox] = fmaxf(acc[oc], 0.f);
}

// ==== fused depthwise 3x3 + relu + pointwise 1x1 + relu + tile pooling ======
// fb is only ever pooled, so never materialize it: block-reduce the 16x16
// tile sum per channel and store into g_part (deterministic, no atomics).
__global__ void dwpw_kernel(const float* __restrict__ wd,
                            const float* __restrict__ bd,
                            const float* __restrict__ wp,
                            const float* __restrict__ bp) {
    __shared__ float s_in[16][18][18];
    __shared__ float s_wd[16][9];
    __shared__ float s_wp[16][16];   // [ic][oc]
    __shared__ float s_bd[16], s_bp[16];
    __shared__ float s_red[8][16];
    const int b = blockIdx.z;
    const int ox0 = blockIdx.x * 16, oy0 = blockIdx.y * 16;
    const int tid = threadIdx.y * 16 + threadIdx.x;

    if (tid < 144) s_wd[tid / 9][tid % 9] = wd[tid];
    {
        int oc = tid >> 4, ic = tid & 15;
        s_wp[ic][oc] = wp[oc * 16 + ic];
    }
    if (tid < 16) { s_bd[tid] = bd[tid]; s_bp[tid] = bp[tid]; }
    for (int i = tid; i < 16 * 324; i += 256) {
        int c = i / 324, r = i % 324;
        int yy = r / 18, xx = r % 18;
        int gy = oy0 + yy - 1, gx = ox0 + xx - 1;
        float v = 0.f;
        if (gy >= 0 && gy < H1 && gx >= 0 && gx < W1)
            v = g_t3[((b * 16 + c) * H1 + gy) * W1 + gx];
        s_in[c][yy][xx] = v;
    }
    __syncthreads();

    const int ty = threadIdx.y, tx = threadIdx.x;
    float dwv[16];
    #pragma unroll
    for (int c = 0; c < 16; c++) {
        float d = s_bd[c];
        #pragma unroll
        for (int ky = 0; ky < 3; ky++)
            #pragma unroll
            for (int kx = 0; kx < 3; kx++)
                d = fmaf(s_in[c][ty + ky][tx + kx], s_wd[c][ky * 3 + kx], d);
        dwv[c] = fmaxf(d, 0.f);
    }
    float acc[16];
    #pragma unroll
    for (int oc = 0; oc < 16; oc++) acc[oc] = s_bp[oc];
    #pragma unroll
    for (int c = 0; c < 16; c++) {
        float v = dwv[c];
        #pragma unroll
        for (int oc = 0; oc < 16; oc++) acc[oc] = fmaf(v, s_wp[c][oc], acc[oc]);
    }
    #pragma unroll
    for (int oc = 0; oc < 16; oc++) acc[oc] = fmaxf(acc[oc], 0.f);

    // ---- reduce tile sum per channel ----
    #pragma unroll
    for (int oc = 0; oc < 16; oc++) {
        float v = acc[oc];
        #pragma unroll
        for (int o = 16; o > 0; o >>= 1) v += __shfl_xor_sync(0xffffffffu, v, o);
        acc[oc] = v;
    }
    const int warp = tid >> 5, lane = tid & 31;
    if (lane == 0) {
        #pragma unroll
        for (int oc = 0; oc < 16; oc++) s_red[warp][oc] = acc[oc];
    }
    __syncthreads();
    if (tid < 16) {
        float s = 0.f;
        #pragma unroll
        for (int w8 = 0; w8 < 8; w8++) s += s_red[w8][tid];
        g_part[(b * 16 + tid) * 64 + blockIdx.y * 8 + blockIdx.x] = s;
    }
}

// -------- combined head coefficients: phi = (phi1+phi2+phi3)/3 --------------
__global__ void phi_kernel(const float* __restrict__ wf1, const float* __restrict__ bf1,
                           const float* __restrict__ wf2, const float* __restrict__ bf2,
                           const float* __restrict__ wf3, const float* __restrict__ bf3) {
    const int b = blockIdx.x;
    const int c = threadIdx.x;
    if (c >= 3) return;
    float S = bf1[c] + bf2[c] + bf3[c];
    for (int ch = 0; ch < 16; ch++) {
        const float* part = &g_part[(b * 16 + ch) * 64];
        float m[16];
        float sum16 = 0.f;
        #pragma unroll
        for (int pi = 0; pi < 4; pi++)
            #pragma unroll
            for (int pj = 0; pj < 4; pj++) {
                int p = pi * 4 + pj;
                float s = part[(2*pi)*8 + 2*pj]     + part[(2*pi)*8 + 2*pj + 1]
                        + part[(2*pi + 1)*8 + 2*pj] + part[(2*pi + 1)*8 + 2*pj + 1];
                m[p] = s * (1.0f / 1024.0f);
                sum16 += m[p];
                S = fmaf(m[p], wf3[c * 256 + ch * 16 + p], S);
            }
        S = fmaf(sum16 * (1.f / 16.f), wf1[c * 16 + ch], S);
        #pragma unroll
        for (int i = 0; i < 2; i++)
            #pragma unroll
            for (int j = 0; j < 2; j++) {
                float f2v = 0.25f * (m[(2 * i) * 4 + 2 * j] + m[(2 * i) * 4 + 2 * j + 1] +
                                     m[(2 * i + 1) * 4 + 2 * j] + m[(2 * i + 1) * 4 + 2 * j + 1]);
                S = fmaf(f2v, wf2[c * 64 + ch * 4 + i * 2 + j], S);
            }
    }
    g_phi[b * 3 + c] = S * (1.f / 3.f);
}

// -------- fused grayscale + horizontal 21-tap Gaussian (reflect-101) --------
__global__ void grayblurh_kernel(const float* __restrict__ x, float* __restrict__ out) {
    __shared__ float row[256];
    __shared__ float sw[21];
    const int b = blockIdx.y, y = blockIdx.x;
    const int tx = threadIdx.x;
    if (tx < 21) {
        float t = (float)tx - 10.f;
        sw[tx] = expf(-(t * t) / 24.5f);
    }
    const float p0 = g_phi[b * 3 + 0], p1 = g_phi[b * 3 + 1], p2 = g_phi[b * 3 + 2];
    const int i = y * 256 + tx;
    float v = p0 * x[(b * 3 + 0) * NPIX0 + i]
            + p1 * x[(b * 3 + 1) * NPIX0 + i]
            + p2 * x[(b * 3 + 2) * NPIX0 + i];
    out[(b * 3 + 1) * NPIX0 + i] = v;   // i_gray (channel 1)
    row[tx] = v;
    __syncthreads();
    float wsum = 0.f;
    #pragma unroll
    for (int t = 0; t < 21; t++) wsum += sw[t];
    float acc = 0.f;
    #pragma unroll
    for (int t = 0; t < 21; t++) {
        int xx = tx + t - 10;
        xx = xx < 0 ? -xx : (xx > 255 ? 510 - xx : xx);
        acc = fmaf(sw[t], row[xx], acc);
    }
    g_tmp[(b * 256 + y) * 256 + tx] = acc / wsum;
}

// -------- vertical 21-tap Gaussian + base/detail writes ---------------------
__global__ void blurv_kernel(float* __restrict__ out) {
    __shared__ float tile[84][32];
    __shared__ float sw[21];
    const int b = blockIdx.z;
    const int x0 = blockIdx.x * 32, y0 = blockIdx.y * 64;
    const int tid = threadIdx.y * 32 + threadIdx.x;
    if (tid < 21) {
        float t = (float)tid - 10.f;
        sw[tid] = expf(-(t * t) / 24.5f);
    }
    for (int i = tid; i < 84 * 32; i += 256) {
        int yy = i / 32, xx = i % 32;
        int gy = y0 + yy - 10;
        gy = gy < 0 ? -gy : (gy > 255 ? 510 - gy : gy);
        tile[yy][xx] = g_tmp[(b * 256 + gy) * 256 + x0 + xx];
    }
    __syncthreads();
    float wsum = 0.f;
    #pragma unroll
    for (int t = 0; t < 21; t++) wsum += sw[t];
    const float inv = 1.f / wsum;
    const int tx = threadIdx.x;
    for (int r = 0; r < 8; r++) {
        const int ly = threadIdx.y * 8 + r;
        float acc = 0.f;
        #pragma unroll
        for (int t = 0; t < 21; t++) acc = fmaf(sw[t], tile[ly + t][tx], acc);
        const float base = acc * inv;
        const int gy = y0 + ly, gx = x0 + tx;
        const int idx = (b * 3) * NPIX0 + gy * 256 + gx;
        const float ig = out[idx + NPIX0];
        out[idx] = base;                  // base   (channel 0)
        out[idx + 2 * NPIX0] = ig - base; // detail (channel 2)
    }
}

// ---------------------------------------------------------------------------
extern "C" void kernel_launch(void* const* d_in, const int* in_sizes, int n_in,
                              void* d_out, int out_size) {
    const float* x   = (const float*)d_in[0];
    const float* w1  = (const float*)d_in[1];
    const float* b1  = (const float*)d_in[2];
    const float* w2  = (const float*)d_in[3];
    const float* b2  = (const float*)d_in[4];
    const float* w3  = (const float*)d_in[5];
    const float* b3  = (const float*)d_in[6];
    const float* wd  = (const float*)d_in[7];
    const float* bd  = (const float*)d_in[8];
    const float* wp  = (const float*)d_in[9];
    const float* bp  = (const float*)d_in[10];
    const float* wf1 = (const float*)d_in[11];
    const float* bf1 = (const float*)d_in[12];
    const float* wf2 = (const float*)d_in[13];
    const float* bf2 = (const float*)d_in[14];
    const float* wf3 = (const float*)d_in[15];
    const float* bf3 = (const float*)d_in[16];
    float* out = (float*)d_out;

    static int smem_set = 0;
    const int c12_smem = C12_SMEM_FLOATS * (int)sizeof(float);
    if (!smem_set) {
        cudaFuncSetAttribute(conv12_kernel,
                             cudaFuncAttributeMaxDynamicSharedMemorySize, c12_smem);
        smem_set = 1;
    }

    conv12_kernel<<<dim3(8, 8, BATCH), dim3(16, 16), c12_smem>>>(x, w1, b1, w2, b2);
    conv3_kernel<<<dim3(8, 8, BATCH), dim3(16, 16)>>>(w3, b3);
    dwpw_kernel<<<dim3(8, 8, BATCH), dim3(16, 16)>>>(wd, bd, wp, bp);
    phi_kernel<<<BATCH, 32>>>(wf1, bf1, wf2, bf2, wf3, bf3);
    grayblurh_kernel<<<dim3(256, BATCH), 256>>>(x, out);
    blurv_kernel<<<dim3(8, 4, BATCH), dim3(32, 8)>>>(out);
}

// round 3
// speedup vs baseline: 1.1020x; 1.1020x over previous
#include <cuda_runtime.h>

#define BATCH 64
#define H0 256
#define W0 256
#define H1 128
#define W1 128
#define NPIX0 (H0*W0)
#define NPIX1 (H1*W1)

// ---------------- scratch (device globals: no allocations allowed) ----------
__device__ float g_t2[BATCH*16*NPIX1];    // conv2 out (67 MB)
__device__ float g_t3[BATCH*16*NPIX1];    // conv3 out (67 MB)
__device__ float g_part[BATCH*16*16];     // 32x32-block sums of fb (pool cells)
__device__ float g_phi[BATCH*3];          // combined head coefficients
__device__ float g_tmp[BATCH*NPIX0];      // horizontal blur intermediate (17 MB)

// =====================================================================
// Fused conv1 (3->16, 3x3, s1, SAME, relu) + conv2 (16->16, 3x3, s2,
// SAME pad_lo=0, relu). One block -> 16x16 conv2 output tile.
// =====================================================================
#define C12_SMEM_FLOATS (3*35*36 + 8*33*34 + 27*16 + 144*16 + 32)

__global__ void conv12_kernel(const float* __restrict__ x,
                              const float* __restrict__ w1,
                              const float* __restrict__ b1,
                              const float* __restrict__ w2,
                              const float* __restrict__ b2) {
    extern __shared__ float sm[];
    float* s_x   = sm;                     // [3][35][36]
    float* s_mid = s_x + 3*35*36;          // [8][33][34]
    float* s_w1  = s_mid + 8*33*34;        // [27][16]
    float* s_w2  = s_w1 + 27*16;           // [144][16]
    float* s_b1  = s_w2 + 144*16;          // [16]
    float* s_b2  = s_b1 + 16;              // [16]

    const int b = blockIdx.z;
    const int oy0 = blockIdx.y * 16, ox0 = blockIdx.x * 16;
    const int iy0 = oy0 * 2, ix0 = ox0 * 2;
    const int tid = threadIdx.y * 16 + threadIdx.x;
    const int ty = threadIdx.y, tx = threadIdx.x;

    for (int i = tid; i < 27*16; i += 256) {
        int oc = i & 15, k = i >> 4;
        s_w1[k*16 + oc] = w1[oc*27 + k];
    }
    for (int i = tid; i < 144*16; i += 256) {
        int oc = i & 15, k = i >> 4;
        s_w2[k*16 + oc] = w2[oc*144 + k];
    }
    if (tid < 16) { s_b1[tid] = b1[tid]; s_b2[tid] = b2[tid]; }

    for (int i = tid; i < 3*35*35; i += 256) {
        int c = i / 1225, r = i % 1225;
        int yy = r / 35, xx = r % 35;
        int gy = iy0 + yy - 1, gx = ix0 + xx - 1;
        float v = 0.f;
        if (gy >= 0 && gy < H0 && gx >= 0 && gx < W0)
            v = x[((b*3 + c)*H0 + gy)*W0 + gx];
        s_x[(c*35 + yy)*36 + xx] = v;
    }

    float acc2[16];
    #pragma unroll
    for (int oc = 0; oc < 16; oc++) acc2[oc] = 0.f;

    for (int occ = 0; occ < 16; occ += 8) {
        __syncthreads();
        // ---- conv1 for channels occ..occ+7 over 33x33 positions ----
        for (int i = tid; i < 33*33; i += 256) {
            int yy = i / 33, xx = i % 33;
            float a[8];
            #pragma unroll
            for (int j = 0; j < 8; j++) a[j] = s_b1[occ + j];
            #pragma unroll
            for (int c = 0; c < 3; c++)
                #pragma unroll
                for (int ky = 0; ky < 3; ky++)
                    #pragma unroll
                    for (int kx = 0; kx < 3; kx++) {
                        float v = s_x[(c*35 + yy + ky)*36 + xx + kx];
                        const float4* wr4 = (const float4*)&s_w1[(c*9 + ky*3 + kx)*16 + occ];
                        float4 wq[2]; wq[0] = wr4[0]; wq[1] = wr4[1];
                        const float* wv = (const float*)wq;
                        #pragma unroll
                        for (int j = 0; j < 8; j++) a[j] = fmaf(v, wv[j], a[j]);
                    }
            bool valid = (iy0 + yy < H0) && (ix0 + xx < W0);
            #pragma unroll
            for (int j = 0; j < 8; j++)
                s_mid[(j*33 + yy)*34 + xx] = valid ? fmaxf(a[j], 0.f) : 0.f;
        }
        __syncthreads();
        // ---- conv2 partial accumulation over these 8 input channels ----
        #pragma unroll
        for (int c = 0; c < 8; c++)
            #pragma unroll
            for (int ky = 0; ky < 3; ky++)
                #pragma unroll
                for (int kx = 0; kx < 3; kx++) {
                    float v = s_mid[(c*33 + 2*ty + ky)*34 + 2*tx + kx];
                    const float4* wr4 = (const float4*)&s_w2[((occ + c)*9 + ky*3 + kx)*16];
                    float4 wq[4]; wq[0]=wr4[0]; wq[1]=wr4[1]; wq[2]=wr4[2]; wq[3]=wr4[3];
                    const float* wv = (const float*)wq;
                    #pragma unroll
                    for (int oc = 0; oc < 16; oc++) acc2[oc] = fmaf(v, wv[oc], acc2[oc]);
                }
    }

    const int oy = oy0 + ty, ox = ox0 + tx;
    #pragma unroll
    for (int oc = 0; oc < 16; oc++)
        g_t2[((b*16 + oc)*H1 + oy)*W1 + ox] = fmaxf(acc2[oc] + s_b2[oc], 0.f);
}

// =====================================================================
// conv3: 16->16, 3x3, s1, SAME, relu. 32x32 tile, 2x2 pixels per thread.
// =====================================================================
#define C3_SMEM_FLOATS (16*34*36 + 144*16 + 16)

__global__ void conv3_kernel(const float* __restrict__ w,
                             const float* __restrict__ bias) {
    extern __shared__ float sm[];
    float* s_in = sm;                 // [16][34][36]
    float* s_w  = s_in + 16*34*36;    // [144][16]
    float* s_b  = s_w + 144*16;       // [16]

    const int b = blockIdx.z;
    const int oy0 = blockIdx.y * 32, ox0 = blockIdx.x * 32;
    const int tid = threadIdx.y * 16 + threadIdx.x;
    const int ty = threadIdx.y, tx = threadIdx.x;

    for (int i = tid; i < 144*16; i += 256) {
        int oc = i & 15, k = i >> 4;
        s_w[k*16 + oc] = w[oc*144 + k];
    }
    if (tid < 16) s_b[tid] = bias[tid];
    for (int i = tid; i < 16*34*34; i += 256) {
        int c = i / 1156, r = i % 1156;
        int yy = r / 34, xx = r % 34;
        int gy = oy0 + yy - 1, gx = ox0 + xx - 1;
        float v = 0.f;
        if (gy >= 0 && gy < H1 && gx >= 0 && gx < W1)
            v = g_t2[((b*16 + c)*H1 + gy)*W1 + gx];
        s_in[(c*34 + yy)*36 + xx] = v;
    }
    __syncthreads();

    float acc0[16], acc1[16], acc2[16], acc3[16];
    #pragma unroll
    for (int oc = 0; oc < 16; oc++) {
        float bb = s_b[oc];
        acc0[oc] = bb; acc1[oc] = bb; acc2[oc] = bb; acc3[oc] = bb;
    }

    #pragma unroll 4
    for (int c = 0; c < 16; c++) {
        const float* base = &s_in[(c*34)*36];
        #pragma unroll
        for (int ky = 0; ky < 3; ky++)
            #pragma unroll
            for (int kx = 0; kx < 3; kx++) {
                const float4* wr4 = (const float4*)&s_w[(c*9 + ky*3 + kx)*16];
                float4 wq[4]; wq[0]=wr4[0]; wq[1]=wr4[1]; wq[2]=wr4[2]; wq[3]=wr4[3];
                const float* wv = (const float*)wq;
                const float* r0 = &base[(2*ty + ky)*36 + 2*tx + kx];
                float v00 = r0[0], v01 = r0[1];
                float v10 = r0[36], v11 = r0[37];
                #pragma unroll
                for (int oc = 0; oc < 16; oc++) {
                    float wvv = wv[oc];
                    acc0[oc] = fmaf(v00, wvv, acc0[oc]);
                    acc1[oc] = fmaf(v01, wvv, acc1[oc]);
                    acc2[oc] = fmaf(v10, wvv, acc2[oc]);
                    acc3[oc] = fmaf(v11, wvv, acc3[oc]);
                }
            }
    }

    const int gy = oy0 + 2*ty, gx = ox0 + 2*tx;
    #pragma unroll
    for (int oc = 0; oc < 16; oc++) {
        float* p0 = &g_t3[((b*16 + oc)*H1 + gy)*W1 + gx];
        float2 r0 = make_float2(fmaxf(acc0[oc], 0.f), fmaxf(acc1[oc], 0.f));
        float2 r1 = make_float2(fmaxf(acc2[oc], 0.f), fmaxf(acc3[oc], 0.f));
        *(float2*)p0 = r0;
        *(float2*)(p0 + W1) = r1;
    }
}

// =====================================================================
// Fused depthwise 3x3 + relu + pointwise 1x1 + relu + 32x32 pool sum.
// 32x32 tile per block = exactly one pool cell. fb never materialized.
// =====================================================================
#define DW_SMEM_FLOATS (16*34*36 + 144 + 256 + 16 + 16 + 128)

__global__ void dwpw_kernel(const float* __restrict__ wd,
                            const float* __restrict__ bd,
                            const float* __restrict__ wp,
                            const float* __restrict__ bp) {
    extern __shared__ float sm[];
    float* s_in  = sm;                  // [16][34][36]
    float* s_wd  = s_in + 16*34*36;     // [16][9]
    float* s_wp  = s_wd + 144;          // [16][16]  [ic][oc]
    float* s_bd  = s_wp + 256;          // [16]
    float* s_bp  = s_bd + 16;           // [16]
    float* s_red = s_bp + 16;           // [8][16]

    const int b = blockIdx.z;
    const int oy0 = blockIdx.y * 32, ox0 = blockIdx.x * 32;
    const int tid = threadIdx.y * 16 + threadIdx.x;
    const int ty = threadIdx.y, tx = threadIdx.x;

    if (tid < 144) s_wd[tid] = wd[tid];
    {
        int oc = tid >> 4, ic = tid & 15;
        s_wp[ic*16 + oc] = wp[oc*16 + ic];
    }
    if (tid < 16) { s_bd[tid] = bd[tid]; s_bp[tid] = bp[tid]; }
    for (int i = tid; i < 16*34*34; i += 256) {
        int c = i / 1156, r = i % 1156;
        int yy = r / 34, xx = r % 34;
        int gy = oy0 + yy - 1, gx = ox0 + xx - 1;
        float v = 0.f;
        if (gy >= 0 && gy < H1 && gx >= 0 && gx < W1)
            v = g_t3[((b*16 + c)*H1 + gy)*W1 + gx];
        s_in[(c*34 + yy)*36 + xx] = v;
    }
    __syncthreads();

    float acc0[16], acc1[16], acc2[16], acc3[16];
    #pragma unroll
    for (int oc = 0; oc < 16; oc++) {
        float bb = s_bp[oc];
        acc0[oc] = bb; acc1[oc] = bb; acc2[oc] = bb; acc3[oc] = bb;
    }

    #pragma unroll 4
    for (int c = 0; c < 16; c++) {
        const float* base = &s_in[(c*34 + 2*ty)*36 + 2*tx];
        float wdc[9];
        #pragma unroll
        for (int k = 0; k < 9; k++) wdc[k] = s_wd[c*9 + k];
        // 4x4 input patch covering the 2x2 output quad
        float vv[4][4];
        #pragma unroll
        for (int iy = 0; iy < 4; iy++)
            #pragma unroll
            for (int ix = 0; ix < 4; ix++)
                vv[iy][ix] = base[iy*36 + ix];
        float dw0 = s_bd[c], dw1 = dw0, dw2 = dw0, dw3 = dw0;
        #pragma unroll
        for (int ky = 0; ky < 3; ky++)
            #pragma unroll
            for (int kx = 0; kx < 3; kx++) {
                float wvv = wdc[ky*3 + kx];
                dw0 = fmaf(vv[ky][kx],     wvv, dw0);
                dw1 = fmaf(vv[ky][kx+1],   wvv, dw1);
                dw2 = fmaf(vv[ky+1][kx],   wvv, dw2);
                dw3 = fmaf(vv[ky+1][kx+1], wvv, dw3);
            }
        dw0 = fmaxf(dw0, 0.f); dw1 = fmaxf(dw1, 0.f);
        dw2 = fmaxf(dw2, 0.f); dw3 = fmaxf(dw3, 0.f);
        const float4* wr4 = (const float4*)&s_wp[c*16];
        float4 wq[4]; wq[0]=wr4[0]; wq[1]=wr4[1]; wq[2]=wr4[2]; wq[3]=wr4[3];
        const float* wv = (const float*)wq;
        #pragma unroll
        for (int oc = 0; oc < 16; oc++) {
            float wvv = wv[oc];
            acc0[oc] = fmaf(dw0, wvv, acc0[oc]);
            acc1[oc] = fmaf(dw1, wvv, acc1[oc]);
            acc2[oc] = fmaf(dw2, wvv, acc2[oc]);
            acc3[oc] = fmaf(dw3, wvv, acc3[oc]);
        }
    }

    // relu + per-thread quad sum, then block reduce to the 32x32 pool sum
    float t[16];
    #pragma unroll
    for (int oc = 0; oc < 16; oc++)
        t[oc] = fmaxf(acc0[oc], 0.f) + fmaxf(acc1[oc], 0.f)
              + fmaxf(acc2[oc], 0.f) + fmaxf(acc3[oc], 0.f);
    #pragma unroll
    for (int oc = 0; oc < 16; oc++) {
        float v = t[oc];
        #pragma unroll
        for (int o = 16; o > 0; o >>= 1) v += __shfl_xor_sync(0xffffffffu, v, o);
        t[oc] = v;
    }
    const int warp = tid >> 5, lane = tid & 31;
    if (lane == 0) {
        #pragma unroll
        for (int oc = 0; oc < 16; oc++) s_red[warp*16 + oc] = t[oc];
    }
    __syncthreads();
    if (tid < 16) {
        float s = 0.f;
        #pragma unroll
        for (int w8 = 0; w8 < 8; w8++) s += s_red[w8*16 + tid];
        g_part[(b*16 + tid)*16 + blockIdx.y*4 + blockIdx.x] = s;
    }
}

// -------- combined head coefficients: phi = (phi1+phi2+phi3)/3 --------------
// 48 active threads: (head c, channel ch) pairs, then reduce over ch.
__global__ void phi_kernel(const float* __restrict__ wf1, const float* __restrict__ bf1,
                           const float* __restrict__ wf2, const float* __restrict__ bf2,
                           const float* __restrict__ wf3, const float* __restrict__ bf3) {
    const int b = blockIdx.x;
    const int t = threadIdx.x;
    const int c = t >> 4, ch = t & 15;
    __shared__ float red[48];
    float S = 0.f;
    if (t < 48) {
        const float* part = &g_part[(b*16 + ch)*16];
        float m[16];
        float sum16 = 0.f;
        #pragma unroll
        for (int p = 0; p < 16; p++) {
            m[p] = part[p] * (1.0f / 1024.0f);
            sum16 += m[p];
            S = fmaf(m[p], wf3[c*256 + ch*16 + p], S);
        }
        S = fmaf(sum16 * (1.f / 16.f), wf1[c*16 + ch], S);
        #pragma unroll
        for (int i = 0; i < 2; i++)
            #pragma unroll
            for (int j = 0; j < 2; j++) {
                float f2v = 0.25f * (m[(2*i)*4 + 2*j] + m[(2*i)*4 + 2*j + 1] +
                                     m[(2*i+1)*4 + 2*j] + m[(2*i+1)*4 + 2*j + 1]);
                S = fmaf(f2v, wf2[c*64 + ch*4 + i*2 + j], S);
            }
        red[t] = S;
    }
    __syncthreads();
    if (t < 3) {
        float tot = bf1[t] + bf2[t] + bf3[t];
        #pragma unroll
        for (int i = 0; i < 16; i++) tot += red[t*16 + i];
        g_phi[b*3 + t] = tot * (1.f / 3.f);
    }
}

// -------- fused grayscale + horizontal 21-tap Gaussian (reflect-101) --------
__global__ void grayblurh_kernel(const float* __restrict__ x, float* __restrict__ out) {
    __shared__ float row[256];
    __shared__ float sw[21];
    const int b = blockIdx.y, y = blockIdx.x;
    const int tx = threadIdx.x;
    if (tx < 21) {
        float t = (float)tx - 10.f;
        sw[tx] = expf(-(t * t) / 24.5f);
    }
    const float p0 = g_phi[b*3 + 0], p1 = g_phi[b*3 + 1], p2 = g_phi[b*3 + 2];
    const int i = y * 256 + tx;
    float v = p0 * x[(b*3 + 0)*NPIX0 + i]
            + p1 * x[(b*3 + 1)*NPIX0 + i]
            + p2 * x[(b*3 + 2)*NPIX0 + i];
    out[(b*3 + 1)*NPIX0 + i] = v;   // i_gray (channel 1)
    row[tx] = v;
    __syncthreads();
    float wsum = 0.f;
    #pragma unroll
    for (int t = 0; t < 21; t++) wsum += sw[t];
    float acc = 0.f;
    #pragma unroll
    for (int t = 0; t < 21; t++) {
        int xx = tx + t - 10;
        xx = xx < 0 ? -xx : (xx > 255 ? 510 - xx : xx);
        acc = fmaf(sw[t], row[xx], acc);
    }
    g_tmp[(b*256 + y)*256 + tx] = acc / wsum;
}

// -------- vertical 21-tap Gaussian + base/detail writes ---------------------
__global__ void blurv_kernel(float* __restrict__ out) {
    __shared__ float tile[84][32];
    __shared__ float sw[21];
    const int b = blockIdx.z;
    const int x0 = blockIdx.x * 32, y0 = blockIdx.y * 64;
    const int tid = threadIdx.y * 32 + threadIdx.x;
    if (tid < 21) {
        float t = (float)tid - 10.f;
        sw[tid] = expf(-(t * t) / 24.5f);
    }
    for (int i = tid; i < 84 * 32; i += 256) {
        int yy = i / 32, xx = i % 32;
        int gy = y0 + yy - 10;
        gy = gy < 0 ? -gy : (gy > 255 ? 510 - gy : gy);
        tile[yy][xx] = g_tmp[(b*256 + gy)*256 + x0 + xx];
    }
    __syncthreads();
    float wsum = 0.f;
    #pragma unroll
    for (int t = 0; t < 21; t++) wsum += sw[t];
    const float inv = 1.f / wsum;
    const int tx = threadIdx.x;
    for (int r = 0; r < 8; r++) {
        const int ly = threadIdx.y * 8 + r;
        float acc = 0.f;
        #pragma unroll
        for (int t = 0; t < 21; t++) acc = fmaf(sw[t], tile[ly + t][tx], acc);
        const float base = acc * inv;
        const int gy = y0 + ly, gx = x0 + tx;
        const int idx = (b*3)*NPIX0 + gy*256 + gx;
        const float ig = out[idx + NPIX0];
        out[idx] = base;                  // base   (channel 0)
        out[idx + 2*NPIX0] = ig - base;   // detail (channel 2)
    }
}

// ---------------------------------------------------------------------------
extern "C" void kernel_launch(void* const* d_in, const int* in_sizes, int n_in,
                              void* d_out, int out_size) {
    const float* x   = (const float*)d_in[0];
    const float* w1  = (const float*)d_in[1];
    const float* b1  = (const float*)d_in[2];
    const float* w2  = (const float*)d_in[3];
    const float* b2  = (const float*)d_in[4];
    const float* w3  = (const float*)d_in[5];
    const float* b3  = (const float*)d_in[6];
    const float* wd  = (const float*)d_in[7];
    const float* bd  = (const float*)d_in[8];
    const float* wp  = (const float*)d_in[9];
    const float* bp  = (const float*)d_in[10];
    const float* wf1 = (const float*)d_in[11];
    const float* bf1 = (const float*)d_in[12];
    const float* wf2 = (const float*)d_in[13];
    const float* bf2 = (const float*)d_in[14];
    const float* wf3 = (const float*)d_in[15];
    const float* bf3 = (const float*)d_in[16];
    float* out = (float*)d_out;

    const int c12_smem = C12_SMEM_FLOATS * (int)sizeof(float);
    const int c3_smem  = C3_SMEM_FLOATS  * (int)sizeof(float);
    const int dw_smem  = DW_SMEM_FLOATS  * (int)sizeof(float);
    cudaFuncSetAttribute(conv12_kernel, cudaFuncAttributeMaxDynamicSharedMemorySize, c12_smem);
    cudaFuncSetAttribute(conv3_kernel,  cudaFuncAttributeMaxDynamicSharedMemorySize, c3_smem);
    cudaFuncSetAttribute(dwpw_kernel,   cudaFuncAttributeMaxDynamicSharedMemorySize, dw_smem);

    conv12_kernel<<<dim3(8, 8, BATCH), dim3(16, 16), c12_smem>>>(x, w1, b1, w2, b2);
    conv3_kernel<<<dim3(4, 4, BATCH), dim3(16, 16), c3_smem>>>(w3, b3);
    dwpw_kernel<<<dim3(4, 4, BATCH), dim3(16, 16), dw_smem>>>(wd, bd, wp, bp);
    phi_kernel<<<BATCH, 64>>>(wf1, bf1, wf2, bf2, wf3, bf3);
    grayblurh_kernel<<<dim3(256, BATCH), 256>>>(x, out);
    blurv_kernel<<<dim3(8, 4, BATCH), dim3(32, 8)>>>(out);
}

// round 5
// speedup vs baseline: 1.1358x; 1.0307x over previous
#include <cuda_runtime.h>

#define BATCH 64
#define H0 256
#define W0 256
#define H1 128
#define W1 128
#define NPIX0 (H0*W0)
#define NPIX1 (H1*W1)

typedef unsigned long long ull;

// ---- packed f32x2 helpers (Blackwell FFMA2: 2 fp32 FMAs per instruction) ----
__device__ __forceinline__ ull f2pack(float a, float b) {
    ull r; asm("mov.b64 %0, {%1, %2};" : "=l"(r) : "f"(a), "f"(b)); return r;
}
__device__ __forceinline__ void ffma2(ull& d, ull a, ull b) {
    asm("fma.rn.f32x2 %0, %1, %2, %0;" : "+l"(d) : "l"(a), "l"(b));
}
__device__ __forceinline__ float2 f2unpack(ull v) {
    float lo, hi; asm("mov.b64 {%0, %1}, %2;" : "=f"(lo), "=f"(hi) : "l"(v));
    return make_float2(lo, hi);
}

// ---------------- scratch (device globals: no allocations allowed) ----------
__device__ float g_t2[BATCH*16*NPIX1];    // conv2 out (67 MB)
__device__ float g_t3[BATCH*16*NPIX1];    // conv3 out (67 MB)
__device__ float g_part[BATCH*16*16];     // 32x32-block sums of fb (pool cells)
__device__ float g_phi[BATCH*3];          // combined head coefficients
__device__ float g_tmp[BATCH*NPIX0];      // horizontal blur intermediate (17 MB)

// =====================================================================
// Fused conv1 (3->16, 3x3, s1, SAME, relu) + conv2 (16->16, 3x3, s2,
// SAME pad_lo=0, relu). One block -> 16x16 conv2 output tile.
// =====================================================================
#define C12_SMEM_FLOATS (3*35*36 + 8*33*34 + 27*16 + 144*16 + 32)

__global__ void __launch_bounds__(256)
conv12_kernel(const float* __restrict__ x,
              const float* __restrict__ w1,
              const float* __restrict__ b1,
              const float* __restrict__ w2,
              const float* __restrict__ b2) {
    extern __shared__ float sm[];
    float* s_x   = sm;                     // [3][35][36]
    float* s_mid = s_x + 3*35*36;          // [8][33][34]
    float* s_w1  = s_mid + 8*33*34;        // [27][16]
    float* s_w2  = s_w1 + 27*16;           // [144][16]
    float* s_b1  = s_w2 + 144*16;          // [16]
    float* s_b2  = s_b1 + 16;              // [16]

    const int b = blockIdx.z;
    const int oy0 = blockIdx.y * 16, ox0 = blockIdx.x * 16;
    const int iy0 = oy0 * 2, ix0 = ox0 * 2;
    const int tid = threadIdx.y * 16 + threadIdx.x;
    const int ty = threadIdx.y, tx = threadIdx.x;

    for (int i = tid; i < 27*16; i += 256) {
        int oc = i & 15, k = i >> 4;
        s_w1[k*16 + oc] = w1[oc*27 + k];
    }
    for (int i = tid; i < 144*16; i += 256) {
        int oc = i & 15, k = i >> 4;
        s_w2[k*16 + oc] = w2[oc*144 + k];
    }
    if (tid < 16) { s_b1[tid] = b1[tid]; s_b2[tid] = b2[tid]; }

    for (int i = tid; i < 3*35*35; i += 256) {
        int c = i / 1225, r = i % 1225;
        int yy = r / 35, xx = r % 35;
        int gy = iy0 + yy - 1, gx = ix0 + xx - 1;
        float v = 0.f;
        if (gy >= 0 && gy < H0 && gx >= 0 && gx < W0)
            v = x[((b*3 + c)*H0 + gy)*W0 + gx];
        s_x[(c*35 + yy)*36 + xx] = v;
    }

    ull accp[8];      // conv2 accumulators: 16 oc as 8 packed pairs
    #pragma unroll
    for (int j = 0; j < 8; j++) accp[j] = 0ull;

    for (int occ = 0; occ < 16; occ += 8) {
        __syncthreads();
        // ---- conv1 for channels occ..occ+7 over 33x33 positions ----
        for (int i = tid; i < 33*33; i += 256) {
            int yy = i / 33, xx = i % 33;
            ull ap[4];
            #pragma unroll
            for (int j = 0; j < 4; j++)
                ap[j] = f2pack(s_b1[occ + 2*j], s_b1[occ + 2*j + 1]);
            #pragma unroll
            for (int c = 0; c < 3; c++)
                #pragma unroll
                for (int ky = 0; ky < 3; ky++)
                    #pragma unroll
                    for (int kx = 0; kx < 3; kx++) {
                        float v = s_x[(c*35 + yy + ky)*36 + xx + kx];
                        ull vb = f2pack(v, v);
                        const ull* wr = (const ull*)&s_w1[(c*9 + ky*3 + kx)*16 + occ];
                        #pragma unroll
                        for (int j = 0; j < 4; j++) ffma2(ap[j], vb, wr[j]);
                    }
            bool valid = (iy0 + yy < H0) && (ix0 + xx < W0);
            #pragma unroll
            for (int j = 0; j < 4; j++) {
                float2 a = f2unpack(ap[j]);
                s_mid[((2*j)*33 + yy)*34 + xx]   = valid ? fmaxf(a.x, 0.f) : 0.f;
                s_mid[((2*j+1)*33 + yy)*34 + xx] = valid ? fmaxf(a.y, 0.f) : 0.f;
            }
        }
        __syncthreads();
        // ---- conv2 partial accumulation over these 8 input channels ----
        #pragma unroll
        for (int c = 0; c < 8; c++)
            #pragma unroll
            for (int ky = 0; ky < 3; ky++)
                #pragma unroll
                for (int kx = 0; kx < 3; kx++) {
                    float v = s_mid[(c*33 + 2*ty + ky)*34 + 2*tx + kx];
                    ull vb = f2pack(v, v);
                    const ull* wr = (const ull*)&s_w2[((occ + c)*9 + ky*3 + kx)*16];
                    #pragma unroll
                    for (int j = 0; j < 8; j++) ffma2(accp[j], vb, wr[j]);
                }
    }

    const int oy = oy0 + ty, ox = ox0 + tx;
    #pragma unroll
    for (int j = 0; j < 8; j++) {
        float2 a = f2unpack(accp[j]);
        g_t2[((b*16 + 2*j)*H1 + oy)*W1 + ox]   = fmaxf(a.x + s_b2[2*j], 0.f);
        g_t2[((b*16 + 2*j+1)*H1 + oy)*W1 + ox] = fmaxf(a.y + s_b2[2*j+1], 0.f);
    }
}

// =====================================================================
// conv3: 16->16, 3x3, s1, SAME, relu. 32x32 tile, 2x2 pixels per thread.
// Packed f32x2: 16 oc -> 8 pairs per pixel.
// =====================================================================
#define C3_SMEM_FLOATS (16*34*36 + 144*16 + 16)

__global__ void __launch_bounds__(256)
conv3_kernel(const float* __restrict__ w,
             const float* __restrict__ bias) {
    extern __shared__ float sm[];
    float* s_in = sm;                 // [16][34][36]
    float* s_w  = s_in + 16*34*36;    // [144][16]
    float* s_b  = s_w + 144*16;       // [16]

    const int b = blockIdx.z;
    const int oy0 = blockIdx.y * 32, ox0 = blockIdx.x * 32;
    const int tid = threadIdx.y * 16 + threadIdx.x;
    const int ty = threadIdx.y, tx = threadIdx.x;

    for (int i = tid; i < 144*16; i += 256) {
        int oc = i & 15, k = i >> 4;
        s_w[k*16 + oc] = w[oc*144 + k];
    }
    if (tid < 16) s_b[tid] = bias[tid];
    for (int i = tid; i < 16*34*34; i += 256) {
        int c = i / 1156, r = i % 1156;
        int yy = r / 34, xx = r % 34;
        int gy = oy0 + yy - 1, gx = ox0 + xx - 1;
        float v = 0.f;
        if (gy >= 0 && gy < H1 && gx >= 0 && gx < W1)
            v = g_t2[((b*16 + c)*H1 + gy)*W1 + gx];
        s_in[(c*34 + yy)*36 + xx] = v;
    }
    __syncthreads();

    ull acc0[8], acc1[8], acc2[8], acc3[8];
    #pragma unroll
    for (int j = 0; j < 8; j++) {
        ull bb = f2pack(s_b[2*j], s_b[2*j+1]);
        acc0[j] = bb; acc1[j] = bb; acc2[j] = bb; acc3[j] = bb;
    }

    #pragma unroll 2
    for (int c = 0; c < 16; c++) {
        const float* base = &s_in[(c*34)*36];
        #pragma unroll
        for (int ky = 0; ky < 3; ky++)
            #pragma unroll
            for (int kx = 0; kx < 3; kx++) {
                const ull* wr = (const ull*)&s_w[(c*9 + ky*3 + kx)*16];
                ull wq[8];
                #pragma unroll
                for (int j = 0; j < 8; j++) wq[j] = wr[j];
                const float* r0 = &base[(2*ty + ky)*36 + 2*tx + kx];
                ull v00 = f2pack(r0[0], r0[0]);
                ull v01 = f2pack(r0[1], r0[1]);
                ull v10 = f2pack(r0[36], r0[36]);
                ull v11 = f2pack(r0[37], r0[37]);
                #pragma unroll
                for (int j = 0; j < 8; j++) {
                    ffma2(acc0[j], v00, wq[j]);
                    ffma2(acc1[j], v01, wq[j]);
                    ffma2(acc2[j], v10, wq[j]);
                    ffma2(acc3[j], v11, wq[j]);
                }
            }
    }

    const int gy = oy0 + 2*ty, gx = ox0 + 2*tx;
    #pragma unroll
    for (int j = 0; j < 8; j++) {
        float2 a0 = f2unpack(acc0[j]), a1 = f2unpack(acc1[j]);
        float2 a2 = f2unpack(acc2[j]), a3 = f2unpack(acc3[j]);
        float* p0 = &g_t3[((b*16 + 2*j)*H1 + gy)*W1 + gx];
        *(float2*)p0        = make_float2(fmaxf(a0.x, 0.f), fmaxf(a1.x, 0.f));
        *(float2*)(p0 + W1) = make_float2(fmaxf(a2.x, 0.f), fmaxf(a3.x, 0.f));
        float* p1 = p0 + NPIX1;
        *(float2*)p1        = make_float2(fmaxf(a0.y, 0.f), fmaxf(a1.y, 0.f));
        *(float2*)(p1 + W1) = make_float2(fmaxf(a2.y, 0.f), fmaxf(a3.y, 0.f));
    }
}

// =====================================================================
// Fused depthwise 3x3 + relu + pointwise 1x1 + relu + 32x32 pool sum.
// =====================================================================
#define DW_SMEM_FLOATS (16*34*36 + 144 + 256 + 16 + 16 + 128)

__global__ void __launch_bounds__(256)
dwpw_kernel(const float* __restrict__ wd,
            const float* __restrict__ bd,
            const float* __restrict__ wp,
            const float* __restrict__ bp) {
    extern __shared__ float sm[];
    float* s_in  = sm;                  // [16][34][36]
    float* s_wd  = s_in + 16*34*36;     // [16][9]
    float* s_wp  = s_wd + 144;          // [16][16]  [ic][oc]
    float* s_bd  = s_wp + 256;          // [16]
    float* s_bp  = s_bd + 16;           // [16]
    float* s_red = s_bp + 16;           // [8][16]

    const int b = blockIdx.z;
    const int oy0 = blockIdx.y * 32, ox0 = blockIdx.x * 32;
    const int tid = threadIdx.y * 16 + threadIdx.x;
    const int ty = threadIdx.y, tx = threadIdx.x;

    if (tid < 144) s_wd[tid] = wd[tid];
    {
        int oc = tid >> 4, ic = tid & 15;
        s_wp[ic*16 + oc] = wp[oc*16 + ic];
    }
    if (tid < 16) { s_bd[tid] = bd[tid]; s_bp[tid] = bp[tid]; }
    for (int i = tid; i < 16*34*34; i += 256) {
        int c = i / 1156, r = i % 1156;
        int yy = r / 34, xx = r % 34;
        int gy = oy0 + yy - 1, gx = ox0 + xx - 1;
        float v = 0.f;
        if (gy >= 0 && gy < H1 && gx >= 0 && gx < W1)
            v = g_t3[((b*16 + c)*H1 + gy)*W1 + gx];
        s_in[(c*34 + yy)*36 + xx] = v;
    }
    __syncthreads();

    ull acc0[8], acc1[8], acc2[8], acc3[8];
    #pragma unroll
    for (int j = 0; j < 8; j++) {
        ull bb = f2pack(s_bp[2*j], s_bp[2*j+1]);
        acc0[j] = bb; acc1[j] = bb; acc2[j] = bb; acc3[j] = bb;
    }

    #pragma unroll 2
    for (int c = 0; c < 16; c++) {
        const float* base = &s_in[(c*34 + 2*ty)*36 + 2*tx];
        float vv[4][4];
        #pragma unroll
        for (int iy = 0; iy < 4; iy++)
            #pragma unroll
            for (int ix = 0; ix < 4; ix++)
                vv[iy][ix] = base[iy*36 + ix];
        // depthwise: pixel pairs {dw0,dw1} and {dw2,dw3}
        ull d01 = f2pack(s_bd[c], s_bd[c]);
        ull d23 = d01;
        #pragma unroll
        for (int ky = 0; ky < 3; ky++)
            #pragma unroll
            for (int kx = 0; kx < 3; kx++) {
                float wvv = s_wd[c*9 + ky*3 + kx];
                ull wb = f2pack(wvv, wvv);
                ull va = f2pack(vv[ky][kx],   vv[ky][kx+1]);
                ull vb = f2pack(vv[ky+1][kx], vv[ky+1][kx+1]);
                ffma2(d01, va, wb);
                ffma2(d23, vb, wb);
            }
        float2 dab = f2unpack(d01), dcd = f2unpack(d23);
        float dw0 = fmaxf(dab.x, 0.f), dw1 = fmaxf(dab.y, 0.f);
        float dw2 = fmaxf(dcd.x, 0.f), dw3 = fmaxf(dcd.y, 0.f);
        ull p0 = f2pack(dw0, dw0), p1 = f2pack(dw1, dw1);
        ull p2 = f2pack(dw2, dw2), p3 = f2pack(dw3, dw3);
        const ull* wr = (const ull*)&s_wp[c*16];
        #pragma unroll
        for (int j = 0; j < 8; j++) {
            ull wq = wr[j];
            ffma2(acc0[j], p0, wq);
            ffma2(acc1[j], p1, wq);
            ffma2(acc2[j], p2, wq);
            ffma2(acc3[j], p3, wq);
        }
    }

    // relu + per-thread quad sum, then block reduce to the 32x32 pool sum
    float t[16];
    #pragma unroll
    for (int j = 0; j < 8; j++) {
        float2 a0 = f2unpack(acc0[j]), a1 = f2unpack(acc1[j]);
        float2 a2 = f2unpack(acc2[j]), a3 = f2unpack(acc3[j]);
        t[2*j]   = fmaxf(a0.x,0.f) + fmaxf(a1.x,0.f) + fmaxf(a2.x,0.f) + fmaxf(a3.x,0.f);
        t[2*j+1] = fmaxf(a0.y,0.f) + fmaxf(a1.y,0.f) + fmaxf(a2.y,0.f) + fmaxf(a3.y,0.f);
    }
    #pragma unroll
    for (int oc = 0; oc < 16; oc++) {
        float v = t[oc];
        #pragma unroll
        for (int o = 16; o > 0; o >>= 1) v += __shfl_xor_sync(0xffffffffu, v, o);
        t[oc] = v;
    }
    const int warp = tid >> 5, lane = tid & 31;
    if (lane == 0) {
        #pragma unroll
        for (int oc = 0; oc < 16; oc++) s_red[warp*16 + oc] = t[oc];
    }
    __syncthreads();
    if (tid < 16) {
        float s = 0.f;
        #pragma unroll
        for (int w8 = 0; w8 < 8; w8++) s += s_red[w8*16 + tid];
        g_part[(b*16 + tid)*16 + blockIdx.y*4 + blockIdx.x] = s;
    }
}

// -------- combined head coefficients: phi = (phi1+phi2+phi3)/3 --------------
__global__ void phi_kernel(const float* __restrict__ wf1, const float* __restrict__ bf1,
                           const float* __restrict__ wf2, const float* __restrict__ bf2,
                           const float* __restrict__ wf3, const float* __restrict__ bf3) {
    const int b = blockIdx.x;
    const int t = threadIdx.x;
    const int c = t >> 4, ch = t & 15;
    __shared__ float red[48];
    float S = 0.f;
    if (t < 48) {
        const float* part = &g_part[(b*16 + ch)*16];
        float m[16];
        float sum16 = 0.f;
        #pragma unroll
        for (int p = 0; p < 16; p++) {
            m[p] = part[p] * (1.0f / 1024.0f);
            sum16 += m[p];
            S = fmaf(m[p], wf3[c*256 + ch*16 + p], S);
        }
        S = fmaf(sum16 * (1.f / 16.f), wf1[c*16 + ch], S);
        #pragma unroll
        for (int i = 0; i < 2; i++)
            #pragma unroll
            for (int j = 0; j < 2; j++) {
                float f2v = 0.25f * (m[(2*i)*4 + 2*j] + m[(2*i)*4 + 2*j + 1] +
                                     m[(2*i+1)*4 + 2*j] + m[(2*i+1)*4 + 2*j + 1]);
                S = fmaf(f2v, wf2[c*64 + ch*4 + i*2 + j], S);
            }
        red[t] = S;
    }
    __syncthreads();
    if (t < 3) {
        float tot = bf1[t] + bf2[t] + bf3[t];
        #pragma unroll
        for (int i = 0; i < 16; i++) tot += red[t*16 + i];
        g_phi[b*3 + t] = tot * (1.f / 3.f);
    }
}

// -------- fused grayscale + horizontal 21-tap Gaussian (reflect-101) --------
__global__ void grayblurh_kernel(const float* __restrict__ x, float* __restrict__ out) {
    __shared__ float row[256];
    __shared__ float sw[21];
    const int b = blockIdx.y, y = blockIdx.x;
    const int tx = threadIdx.x;
    if (tx < 21) {
        float t = (float)tx - 10.f;
        sw[tx] = expf(-(t * t) / 24.5f);
    }
    const float p0 = g_phi[b*3 + 0], p1 = g_phi[b*3 + 1], p2 = g_phi[b*3 + 2];
    const int i = y * 256 + tx;
    float v = p0 * x[(b*3 + 0)*NPIX0 + i]
            + p1 * x[(b*3 + 1)*NPIX0 + i]
            + p2 * x[(b*3 + 2)*NPIX0 + i];
    out[(b*3 + 1)*NPIX0 + i] = v;   // i_gray (channel 1)
    row[tx] = v;
    __syncthreads();
    float wsum = 0.f;
    #pragma unroll
    for (int t = 0; t < 21; t++) wsum += sw[t];
    float acc = 0.f;
    #pragma unroll
    for (int t = 0; t < 21; t++) {
        int xx = tx + t - 10;
        xx = xx < 0 ? -xx : (xx > 255 ? 510 - xx : xx);
        acc = fmaf(sw[t], row[xx], acc);
    }
    g_tmp[(b*256 + y)*256 + tx] = acc / wsum;
}

// -------- vertical 21-tap Gaussian + base/detail writes ---------------------
__global__ void blurv_kernel(float* __restrict__ out) {
    __shared__ float tile[84][32];
    __shared__ float sw[21];
    const int b = blockIdx.z;
    const int x0 = blockIdx.x * 32, y0 = blockIdx.y * 64;
    const int tid = threadIdx.y * 32 + threadIdx.x;
    if (tid < 21) {
        float t = (float)tid - 10.f;
        sw[tid] = expf(-(t * t) / 24.5f);
    }
    for (int i = tid; i < 84 * 32; i += 256) {
        int yy = i / 32, xx = i % 32;
        int gy = y0 + yy - 10;
        gy = gy < 0 ? -gy : (gy > 255 ? 510 - gy : gy);
        tile[yy][xx] = g_tmp[(b*256 + gy)*256 + x0 + xx];
    }
    __syncthreads();
    float wsum = 0.f;
    #pragma unroll
    for (int t = 0; t < 21; t++) wsum += sw[t];
    const float inv = 1.f / wsum;
    const int tx = threadIdx.x;
    for (int r = 0; r < 8; r++) {
        const int ly = threadIdx.y * 8 + r;
        float acc = 0.f;
        #pragma unroll
        for (int t = 0; t < 21; t++) acc = fmaf(sw[t], tile[ly + t][tx], acc);
        const float base = acc * inv;
        const int gy = y0 + ly, gx = x0 + tx;
        const int idx = (b*3)*NPIX0 + gy*256 + gx;
        const float ig = out[idx + NPIX0];
        out[idx] = base;                  // base   (channel 0)
        out[idx + 2*NPIX0] = ig - base;   // detail (channel 2)
    }
}

// ---------------------------------------------------------------------------
extern "C" void kernel_launch(void* const* d_in, const int* in_sizes, int n_in,
                              void* d_out, int out_size) {
    const float* x   = (const float*)d_in[0];
    const float* w1  = (const float*)d_in[1];
    const float* b1  = (const float*)d_in[2];
    const float* w2  = (const float*)d_in[3];
    const float* b2  = (const float*)d_in[4];
    const float* w3  = (const float*)d_in[5];
    const float* b3  = (const float*)d_in[6];
    const float* wd  = (const float*)d_in[7];
    const float* bd  = (const float*)d_in[8];
    const float* wp  = (const float*)d_in[9];
    const float* bp  = (const float*)d_in[10];
    const float* wf1 = (const float*)d_in[11];
    const float* bf1 = (const float*)d_in[12];
    const float* wf2 = (const float*)d_in[13];
    const float* bf2 = (const float*)d_in[14];
    const float* wf3 = (const float*)d_in[15];
    const float* bf3 = (const float*)d_in[16];
    float* out = (float*)d_out;

    const int c12_smem = C12_SMEM_FLOATS * (int)sizeof(float);
    const int c3_smem  = C3_SMEM_FLOATS  * (int)sizeof(float);
    const int dw_smem  = DW_SMEM_FLOATS  * (int)sizeof(float);
    cudaFuncSetAttribute(conv12_kernel, cudaFuncAttributeMaxDynamicSharedMemorySize, c12_smem);
    cudaFuncSetAttribute(conv3_kernel,  cudaFuncAttributeMaxDynamicSharedMemorySize, c3_smem);
    cudaFuncSetAttribute(dwpw_kernel,   cudaFuncAttributeMaxDynamicSharedMemorySize, dw_smem);

    conv12_kernel<<<dim3(8, 8, BATCH), dim3(16, 16), c12_smem>>>(x, w1, b1, w2, b2);
    conv3_kernel<<<dim3(4, 4, BATCH), dim3(16, 16), c3_smem>>>(w3, b3);
    dwpw_kernel<<<dim3(4, 4, BATCH), dim3(16, 16), dw_smem>>>(wd, bd, wp, bp);
    phi_kernel<<<BATCH, 64>>>(wf1, bf1, wf2, bf2, wf3, bf3);
    grayblurh_kernel<<<dim3(256, BATCH), 256>>>(x, out);
    blurv_kernel<<<dim3(8, 4, BATCH), dim3(32, 8)>>>(out);
}